// round 7
// baseline (speedup 1.0000x reference)
#include <cuda_runtime.h>

// Problem constants (from reference)
#define NWIN   16
#define NSTEP  16          // 1 + NG + NF
#define NP     256         // NWIN * NSTEP pairs
#define TT     400
#define DIMV   64
#define NG     5
#define NF     10
#define BIG_F   1e10f
#define TILE    80         // 400 = 5 * 80, zero edge waste
#define SSTRIDE 84         // k-major smem row stride (16B-aligned)
#define DTHREADS 400       // 20x20 threads, 4x4 microtile

// exp/log base-2 folded constants:
//   exp((m-x)/g) = exp2((m-x) * C1),  C1 = log2(e)/g
//   g*ln(s)      = C2 * log2(s),      C2 = g*ln(2)
#define C1_F 0.28853900817779268f
#define C2_F 3.4657359027997265f

// Scratch: __device__ globals (no cudaMalloc allowed)
__device__ float g_D[(size_t)NP * TT * TT];   // 163.84 MB cost matrices
__device__ float g_norm[NP * TT];             // per-row squared norms
__device__ float g_dists[NP];                 // soft-DTW distances

// ncu capture = launch index 3 of the call; probe0 pads index 2 so dp_kernel
// stays at the profiled slot.
__global__ void probe0_kernel() {}

// ---------------------------------------------------------------------------
// Phase 0: row squared norms. One warp per (pair,row); 2 loads + shuffle tree.
// ---------------------------------------------------------------------------
__global__ void norm_kernel(const float* __restrict__ data) {
    int w = blockIdx.x * (blockDim.x >> 5) + (threadIdx.x >> 5);
    int lane = threadIdx.x & 31;
    const float* row = data + (size_t)w * DIMV;
    float v0 = row[lane];
    float v1 = row[lane + 32];
    float s = v0 * v0 + v1 * v1;
    #pragma unroll
    for (int o = 16; o > 0; o >>= 1) s += __shfl_xor_sync(0xffffffffu, s, o);
    if (lane == 0) g_norm[w] = s;
}

// ---------------------------------------------------------------------------
// Phase 1: D[p][i][j] = na[i] + nb[j] - 2 * dot(A_i, B_j)
// 80x80 tile per CTA, 400 threads, 4x4 microtile, k-major smem (2x LDS.128 +
// 16 FFMA per k). Tiles outside the [0,la)x[0,lb) DP box are skipped.
// ---------------------------------------------------------------------------
__global__ __launch_bounds__(DTHREADS) void d_kernel(const float* __restrict__ data,
                                                     const int* __restrict__ lens) {
    int p  = blockIdx.z;
    int ti = blockIdx.y, tj = blockIdx.x;

    int la = __ldg(&lens[p & ~(NSTEP - 1)]);
    int lb = __ldg(&lens[p]);
    if (ti * TILE >= la || tj * TILE >= lb) return;   // dead tile

    const float* A = data + (size_t)(p & ~(NSTEP - 1)) * TT * DIMV;  // window anchor
    const float* B = data + (size_t)p * TT * DIMV;

    __shared__ float As[DIMV][SSTRIDE];   // k-major: As[k][row]
    __shared__ float Bs[DIMV][SSTRIDE];

    int tid = threadIdx.x;
    for (int it = tid; it < TILE * 16; it += DTHREADS) {
        int row = it >> 4, c4 = (it & 15) * 4;
        float4 va = *(const float4*)(A + (size_t)(ti * TILE + row) * DIMV + c4);
        float4 vb = *(const float4*)(B + (size_t)(tj * TILE + row) * DIMV + c4);
        As[c4 + 0][row] = va.x; As[c4 + 1][row] = va.y;
        As[c4 + 2][row] = va.z; As[c4 + 3][row] = va.w;
        Bs[c4 + 0][row] = vb.x; Bs[c4 + 1][row] = vb.y;
        Bs[c4 + 2][row] = vb.z; Bs[c4 + 3][row] = vb.w;
    }
    __syncthreads();

    int tx = tid % 20, ty = tid / 20;   // 20x20 grid of 4x4 microtiles
    float acc[4][4];
    #pragma unroll
    for (int r = 0; r < 4; r++)
        #pragma unroll
        for (int c = 0; c < 4; c++) acc[r][c] = 0.0f;

    #pragma unroll 4
    for (int k = 0; k < DIMV; k++) {
        float4 a4 = *(const float4*)&As[k][ty * 4];
        float4 b4 = *(const float4*)&Bs[k][tx * 4];
        float a[4] = {a4.x, a4.y, a4.z, a4.w};
        float b[4] = {b4.x, b4.y, b4.z, b4.w};
        #pragma unroll
        for (int r = 0; r < 4; r++)
            #pragma unroll
            for (int c = 0; c < 4; c++) acc[r][c] += a[r] * b[c];
    }

    const float* nA = g_norm + (p & ~(NSTEP - 1)) * TT + ti * TILE + ty * 4;
    const float* nB = g_norm + p * TT + tj * TILE + tx * 4;
    float na[4], nb[4];
    #pragma unroll
    for (int r = 0; r < 4; r++) na[r] = nA[r];
    #pragma unroll
    for (int c = 0; c < 4; c++) nb[c] = nB[c];

    float* Dp = g_D + (size_t)p * TT * TT;
    #pragma unroll
    for (int r = 0; r < 4; r++) {
        int gi = ti * TILE + ty * 4 + r;
        int gj = tj * TILE + tx * 4;
        float4 o;
        o.x = na[r] + nb[0] - 2.0f * acc[r][0];
        o.y = na[r] + nb[1] - 2.0f * acc[r][1];
        o.z = na[r] + nb[2] - 2.0f * acc[r][2];
        o.w = na[r] + nb[3] - 2.0f * acc[r][3];
        *(float4*)(Dp + (size_t)gi * TT + gj) = o;
    }
}

// ---------------------------------------------------------------------------
// soft-DTW cell. NOTE: keep (m-x)*C1 (FADD->FMUL). An fmaf refactor of the
// exponent can round BIG-BIG to +-128 -> exp2=inf -> -inf poison.
// m <= x always, so exp2 args are <= 0 and s in [1, 3+eps]: no overflow.
// ---------------------------------------------------------------------------
__device__ __forceinline__ float sdtw_cell(float a, float b, float c, float d) {
    float m = fminf(a, fminf(b, c));
    float s = exp2f((m - a) * C1_F)
            + exp2f((m - b) * C1_F)
            + exp2f((m - c) * C1_F);
    return d + m - C2_F * __log2f(s);
}

// ---------------------------------------------------------------------------
// Phase 2: blocked-wavefront soft-DTW. One CTA per pair, 128 threads.
// Thread t owns DP rows i0..i0+3 (i0 = 4t+1). Super-step S computes the 4x4
// block (t, S-t): 16 cells, covering 4 anti-diagonals per __syncthreads
// (<=198 barriers vs <=800 in the per-diagonal version). Cross-thread data is
// one float4 (neighbor's bottom row, double-buffered by step parity) plus a
// register-carried corner; left column stays in registers; D comes in as 4
// prefetched LDG.128. Masked cells write exact BIG (reference boundary
// semantics); out-of-box cells never feed in-box cells.
// ---------------------------------------------------------------------------
__global__ __launch_bounds__(128) void dp_kernel(const int* __restrict__ lens) {
    int p  = blockIdx.x;
    int la = lens[p & ~(NSTEP - 1)];
    int lb = lens[p];
    int t  = threadIdx.x;

    __shared__ float bot[2][104][4];   // [parity][thread][bottom row of block]

    const float* Dp = g_D + (size_t)p * TT * TT;
    int bimax = (la - 1) >> 2;         // last block-row index
    int bjmax = (lb - 1) >> 2;         // last block-col index
    int Smax  = bimax + bjmax;

    bool rowok = (t <= bimax);
    int  i0 = 4 * t + 1;
    const float* drow0 = Dp + (size_t)(4 * t) * TT;   // D row i0-1

    float left[4], K = BIG_F;
    float4 d0, d1, d2, d3;             // prefetched D rows 4t..4t+3, 4 cols

    if (rowok) {                        // prefetch block col 0 (cols 0..3)
        d0 = *(const float4*)(drow0);
        d1 = *(const float4*)(drow0 + TT);
        d2 = *(const float4*)(drow0 + 2 * TT);
        d3 = *(const float4*)(drow0 + 3 * TT);
    }

    float inv = 1.0f / (float)(la + lb);

    for (int S = 0; S <= Smax; S++) {
        int  bj  = S - t;
        bool act = rowok && (bj >= 0) && (bj <= bjmax);
        int  par = S & 1;

        if (act) {
            int j0 = 4 * bj + 1;

            // top row R[i0-1][j0-1 .. j0+3]: corner K + 4 values from neighbor
            float top[5];
            top[0] = K;
            if (t == 0) {
                top[1] = BIG_F; top[2] = BIG_F; top[3] = BIG_F; top[4] = BIG_F;
            } else {
                float4 tv = *(const float4*)&bot[par ^ 1][t - 1][0];
                top[1] = tv.x; top[2] = tv.y; top[3] = tv.z; top[4] = tv.w;
            }
            if (bj == 0) {              // first active step: left boundary
                left[0] = BIG_F; left[1] = BIG_F; left[2] = BIG_F; left[3] = BIG_F;
                top[0] = (t == 0) ? 0.0f : BIG_F;   // R[i0-1][0]
            }

            float d[4][4];
            d[0][0]=d0.x; d[0][1]=d0.y; d[0][2]=d0.z; d[0][3]=d0.w;
            d[1][0]=d1.x; d[1][1]=d1.y; d[1][2]=d1.z; d[1][3]=d1.w;
            d[2][0]=d2.x; d[2][1]=d2.y; d[2][2]=d2.z; d[2][3]=d2.w;
            d[3][0]=d3.x; d[3][1]=d3.y; d[3][2]=d3.z; d[3][3]=d3.w;

            bool rv[4], cv[4];
            #pragma unroll
            for (int r = 0; r < 4; r++) rv[r] = (i0 + r) <= la;
            #pragma unroll
            for (int c = 0; c < 4; c++) cv[c] = (j0 + c) <= lb;

            float cur[4][4];
            #pragma unroll
            for (int r = 0; r < 4; r++) {
                #pragma unroll
                for (int c = 0; c < 4; c++) {
                    float aa = (r == 0) ? top[c]
                             : (c == 0) ? left[r - 1] : cur[r - 1][c - 1];
                    float bb = (r == 0) ? top[c + 1] : cur[r - 1][c];
                    float cc = (c == 0) ? left[r]    : cur[r][c - 1];
                    float v  = sdtw_cell(aa, bb, cc, d[r][c]);
                    cur[r][c] = (rv[r] && cv[c]) ? v : BIG_F;
                }
            }

            // carry state to next block in this row
            K = top[4];
            #pragma unroll
            for (int r = 0; r < 4; r++) left[r] = cur[r][3];
            *(float4*)&bot[par][t][0] =
                make_float4(cur[3][0], cur[3][1], cur[3][2], cur[3][3]);

            // final cell (la, lb) lives in block (bimax, bjmax)
            if (t == bimax && bj == bjmax) {
                int ri = (la - 1) & 3, ci = (lb - 1) & 3;
                float out = cur[3][3];
                #pragma unroll
                for (int r = 0; r < 4; r++)
                    #pragma unroll
                    for (int c = 0; c < 4; c++)
                        if (ri == r && ci == c) out = cur[r][c];
                g_dists[p] = out * inv;
            }

            // prefetch next block's D (cols 4*(bj+1)) before the barrier
            if (bj < bjmax) {
                const float* dc = drow0 + 4 * (bj + 1);
                d0 = *(const float4*)(dc);
                d1 = *(const float4*)(dc + TT);
                d2 = *(const float4*)(dc + 2 * TT);
                d3 = *(const float4*)(dc + 3 * TT);
            }
        }
        __syncthreads();
    }
}

// ---------------------------------------------------------------------------
// Phase 3: contrastive loss over 16 windows -> scalar mean.
// ---------------------------------------------------------------------------
__global__ void reduce_kernel(const float* __restrict__ margin,
                              float* __restrict__ out) {
    __shared__ float lv[NWIN];
    int tid = threadIdx.x;
    if (tid < NWIN) {
        const float* dw = g_dists + tid * NSTEP;
        float daa = dw[0];
        float mg  = margin[0];
        float ssum = 0.0f;
        int nz = 1;
        #pragma unroll
        for (int s = 1; s <= NG; s++) {
            float v = dw[s] - daa;
            ssum += v;
            nz += (v != 0.0f);
        }
        #pragma unroll
        for (int s = 1 + NG; s < 1 + NG + NF; s++) {
            float v = mg - (dw[s] - daa);
            v = fmaxf(v, 0.0f);
            ssum += v;
            nz += (v != 0.0f);
        }
        lv[tid] = ssum / (float)nz;
    }
    __syncthreads();
    if (tid == 0) {
        float tsum = 0.0f;
        #pragma unroll
        for (int w = 0; w < NWIN; w++) tsum += lv[w];
        out[0] = tsum * (1.0f / NWIN);
    }
}

// ---------------------------------------------------------------------------
extern "C" void kernel_launch(void* const* d_in, const int* in_sizes, int n_in,
                              void* d_out, int out_size) {
    const float* data   = (const float*)d_in[0];
    const float* margin = (const float*)d_in[1];
    const int*   lens   = (const int*)d_in[2];
    float*       out    = (float*)d_out;

    norm_kernel<<<(NP * TT) / 8, 256>>>(data);             // idx 0
    d_kernel<<<dim3(5, 5, NP), DTHREADS>>>(data, lens);    // idx 1
    probe0_kernel<<<1, 32>>>();                            // idx 2 (pad)
    dp_kernel<<<NP, 128>>>(lens);                          // idx 3 <- ncu capture slot
    reduce_kernel<<<1, 32>>>(margin, out);                 // idx 4
}

// round 8
// speedup vs baseline: 1.1675x; 1.1675x over previous
#include <cuda_runtime.h>

// Problem constants (from reference)
#define NWIN   16
#define NSTEP  16          // 1 + NG + NF
#define NP     256         // NWIN * NSTEP pairs
#define TT     400
#define DIMV   64
#define NG     5
#define NF     10
#define BIG_F   1e10f
#define TILE    80         // 400 = 5 * 80, zero edge waste
#define SSTRIDE 84         // k-major smem row stride (16B-aligned)
#define DTHREADS 400       // 20x20 threads, 4x4 microtile

// dp geometry: 13 warps x 32 rows/warp = 416 rows; G diagonals per super-step
#define DPW  13
#define DPG  8

// exp/log base-2 folded constants:
//   exp((m-x)/g) = exp2((m-x) * C1),  C1 = log2(e)/g
//   g*ln(s)      = C2 * log2(s),      C2 = g*ln(2)
#define C1_F 0.28853900817779268f
#define C2_F 3.4657359027997265f

// Scratch: __device__ globals (no cudaMalloc allowed)
__device__ float g_D[(size_t)NP * TT * TT];   // 163.84 MB cost matrices
__device__ float g_norm[NP * TT];             // per-row squared norms
__device__ float g_dists[NP];                 // soft-DTW distances

// ncu capture = launch index 3 of the call; probe0 pads index 2 so dp_kernel
// stays at the profiled slot.
__global__ void probe0_kernel() {}

// ---------------------------------------------------------------------------
// Phase 0: row squared norms. One warp per (pair,row); 2 loads + shuffle tree.
// ---------------------------------------------------------------------------
__global__ void norm_kernel(const float* __restrict__ data) {
    int w = blockIdx.x * (blockDim.x >> 5) + (threadIdx.x >> 5);
    int lane = threadIdx.x & 31;
    const float* row = data + (size_t)w * DIMV;
    float v0 = row[lane];
    float v1 = row[lane + 32];
    float s = v0 * v0 + v1 * v1;
    #pragma unroll
    for (int o = 16; o > 0; o >>= 1) s += __shfl_xor_sync(0xffffffffu, s, o);
    if (lane == 0) g_norm[w] = s;
}

// ---------------------------------------------------------------------------
// Phase 1: D[p][i][j] = na[i] + nb[j] - 2 * dot(A_i, B_j)
// 80x80 tile per CTA, 400 threads, 4x4 microtile, k-major smem (2x LDS.128 +
// 16 FFMA per k). Tiles outside the [0,la)x[0,lb) DP box are skipped.
// ---------------------------------------------------------------------------
__global__ __launch_bounds__(DTHREADS) void d_kernel(const float* __restrict__ data,
                                                     const int* __restrict__ lens) {
    int p  = blockIdx.z;
    int ti = blockIdx.y, tj = blockIdx.x;

    int la = __ldg(&lens[p & ~(NSTEP - 1)]);
    int lb = __ldg(&lens[p]);
    if (ti * TILE >= la || tj * TILE >= lb) return;   // dead tile

    const float* A = data + (size_t)(p & ~(NSTEP - 1)) * TT * DIMV;  // window anchor
    const float* B = data + (size_t)p * TT * DIMV;

    __shared__ float As[DIMV][SSTRIDE];   // k-major: As[k][row]
    __shared__ float Bs[DIMV][SSTRIDE];

    int tid = threadIdx.x;
    for (int it = tid; it < TILE * 16; it += DTHREADS) {
        int row = it >> 4, c4 = (it & 15) * 4;
        float4 va = *(const float4*)(A + (size_t)(ti * TILE + row) * DIMV + c4);
        float4 vb = *(const float4*)(B + (size_t)(tj * TILE + row) * DIMV + c4);
        As[c4 + 0][row] = va.x; As[c4 + 1][row] = va.y;
        As[c4 + 2][row] = va.z; As[c4 + 3][row] = va.w;
        Bs[c4 + 0][row] = vb.x; Bs[c4 + 1][row] = vb.y;
        Bs[c4 + 2][row] = vb.z; Bs[c4 + 3][row] = vb.w;
    }
    __syncthreads();

    int tx = tid % 20, ty = tid / 20;   // 20x20 grid of 4x4 microtiles
    float acc[4][4];
    #pragma unroll
    for (int r = 0; r < 4; r++)
        #pragma unroll
        for (int c = 0; c < 4; c++) acc[r][c] = 0.0f;

    #pragma unroll 4
    for (int k = 0; k < DIMV; k++) {
        float4 a4 = *(const float4*)&As[k][ty * 4];
        float4 b4 = *(const float4*)&Bs[k][tx * 4];
        float a[4] = {a4.x, a4.y, a4.z, a4.w};
        float b[4] = {b4.x, b4.y, b4.z, b4.w};
        #pragma unroll
        for (int r = 0; r < 4; r++)
            #pragma unroll
            for (int c = 0; c < 4; c++) acc[r][c] += a[r] * b[c];
    }

    const float* nA = g_norm + (p & ~(NSTEP - 1)) * TT + ti * TILE + ty * 4;
    const float* nB = g_norm + p * TT + tj * TILE + tx * 4;
    float na[4], nb[4];
    #pragma unroll
    for (int r = 0; r < 4; r++) na[r] = nA[r];
    #pragma unroll
    for (int c = 0; c < 4; c++) nb[c] = nB[c];

    float* Dp = g_D + (size_t)p * TT * TT;
    #pragma unroll
    for (int r = 0; r < 4; r++) {
        int gi = ti * TILE + ty * 4 + r;
        int gj = tj * TILE + tx * 4;
        float4 o;
        o.x = na[r] + nb[0] - 2.0f * acc[r][0];
        o.y = na[r] + nb[1] - 2.0f * acc[r][1];
        o.z = na[r] + nb[2] - 2.0f * acc[r][2];
        o.w = na[r] + nb[3] - 2.0f * acc[r][3];
        *(float4*)(Dp + (size_t)gi * TT + gj) = o;
    }
}

// ---------------------------------------------------------------------------
// soft-DTW cell. NOTE: keep (m-x)*C1 (FADD->FMUL); an fmaf refactor can round
// BIG-BIG exponents to +-128 -> exp2=inf -> -inf poison. m <= x always, so
// exp2 args <= 0 and s in [1, 3]: no overflow.
// ---------------------------------------------------------------------------
__device__ __forceinline__ float sdtw_cell(float a, float b, float c, float d) {
    float m = fminf(a, fminf(b, c));
    float s = exp2f((m - a) * C1_F)
            + exp2f((m - b) * C1_F)
            + exp2f((m - c) * C1_F);
    return d + m - C2_F * __log2f(s);
}

// ---------------------------------------------------------------------------
// Phase 2: pipelined warp-shuffle soft-DTW wavefront. One CTA per pair,
// 416 threads (13 warps -> same occupancy as the best per-diagonal version).
// Lane owns row i = tid+1. Warp w is skewed DPG diagonals behind warp w-1;
// super-step s: warp w processes diagonals [2+(s-w)G, +G).
//
// Register state per lane (before processing diag k):
//   r1   = R[i  ][k-1-i]   (diag k-1, own row)
//   r1m1 = R[i-1][k-1-i+1] (diag k-1, row above)  <- shfl_up / smem boundary
//   r2m1 = R[i-1][k-2-i+1] (diag k-2, row above)  <- carried (prev r1m1)
// Cross-warp boundary (lane31 -> next warp's lane0) via double-buffered smem,
// written at step s parity s&1, read next step at parity (s+1)&1.
//
// Band skip: warp w only executes steps overlapping diags [32w+1, 32w+32+lb]
// (outside: all its cells are masked BIG and neighbors' stale boundary reads
// only feed masked cells). Result R[la][lb] is captured IN-LOOP at the
// iteration where (i==la, j==lb), before later masked iterations overwrite r1.
// ---------------------------------------------------------------------------
__global__ __launch_bounds__(416) void dp_kernel(const int* __restrict__ lens) {
    int p  = blockIdx.x;
    int la = lens[p & ~(NSTEP - 1)];
    int lb = lens[p];
    int t  = threadIdx.x;
    int lane = t & 31;
    int w    = t >> 5;
    int i    = t + 1;                 // DP row owned by this lane (1..416)
    int kmax = la + lb;
    float inv = 1.0f / (float)kmax;

    __shared__ float bnd[2][DPW][DPG];
    if (t < 2 * DPW * DPG) ((float*)bnd)[t] = BIG_F;
    __syncthreads();

    const float* Drow = g_D + (size_t)p * TT * TT
                      + (size_t)((i - 1 < TT - 1) ? (i - 1) : (TT - 1)) * TT;
    bool rowok = (i <= la);

    float r1   = BIG_F;                       // R[i][1-i] (j<=0 -> BIG)
    float r1m1 = BIG_F;                       // R[i-1][2-i]
    float r2m1 = (t == 0) ? 0.0f : BIG_F;     // R[0][0]=0 seeds warp0 lane0

    int wstart = 32 * w + 1;                  // first diag this warp matters for
    int wend   = 32 * w + 32 + lb;            // last diag with any valid cell
    int smax   = (DPW - 1) + (kmax - 2) / DPG;

    for (int s = 0; s <= smax; s++) {
        int a = 2 + (s - w) * DPG;            // first diag of this super-step
        bool act = (s >= w) && (a <= kmax)
                && (a + DPG - 1 >= wstart) && (a <= wend);
        if (act) {
            int n = kmax - a + 1; if (n > DPG) n = DPG;

            // preload D: row i-1, cols (a+d-i-1); coalesced (lane-descending),
            // clamped loads are only consumed by masked cells.
            float dv[DPG];
            int c0 = a - i - 1;
            #pragma unroll
            for (int d = 0; d < DPG; d++) {
                int c = c0 + d;
                c = c < 0 ? 0 : (c > TT - 1 ? TT - 1 : c);
                dv[d] = __ldg(&Drow[c]);
            }

            const float* bprev = bnd[(s + 1) & 1][w > 0 ? w - 1 : 0];
            float*       bout  = bnd[s & 1][w];

            #pragma unroll
            for (int d = 0; d < DPG; d++) {
                if (d < n) {                   // warp-uniform
                    int k = a + d;
                    int j = k - i;
                    bool valid = rowok && (j >= 1) && (j <= lb);
                    float v  = sdtw_cell(r2m1, r1m1, r1, dv[d]);
                    float rn = valid ? v : BIG_F;
                    if (valid && j == lb && i == la)
                        g_dists[p] = rn * inv;         // R[la][lb]/(la+lb)
                    if (lane == 31) bout[d] = rn;      // boundary to warp w+1
                    // advance state to diag k
                    r2m1 = r1m1;
                    float sh = __shfl_up_sync(0xffffffffu, rn, 1);
                    float b0 = (w == 0) ? BIG_F : bprev[d];  // R[32w][k]
                    r1m1 = (lane == 0) ? b0 : sh;
                    r1 = rn;
                }
            }
        }
        __syncthreads();
    }
}

// ---------------------------------------------------------------------------
// Phase 3: contrastive loss over 16 windows -> scalar mean.
// ---------------------------------------------------------------------------
__global__ void reduce_kernel(const float* __restrict__ margin,
                              float* __restrict__ out) {
    __shared__ float lv[NWIN];
    int tid = threadIdx.x;
    if (tid < NWIN) {
        const float* dw = g_dists + tid * NSTEP;
        float daa = dw[0];
        float mg  = margin[0];
        float ssum = 0.0f;
        int nz = 1;
        #pragma unroll
        for (int s = 1; s <= NG; s++) {
            float v = dw[s] - daa;
            ssum += v;
            nz += (v != 0.0f);
        }
        #pragma unroll
        for (int s = 1 + NG; s < 1 + NG + NF; s++) {
            float v = mg - (dw[s] - daa);
            v = fmaxf(v, 0.0f);
            ssum += v;
            nz += (v != 0.0f);
        }
        lv[tid] = ssum / (float)nz;
    }
    __syncthreads();
    if (tid == 0) {
        float tsum = 0.0f;
        #pragma unroll
        for (int w = 0; w < NWIN; w++) tsum += lv[w];
        out[0] = tsum * (1.0f / NWIN);
    }
}

// ---------------------------------------------------------------------------
extern "C" void kernel_launch(void* const* d_in, const int* in_sizes, int n_in,
                              void* d_out, int out_size) {
    const float* data   = (const float*)d_in[0];
    const float* margin = (const float*)d_in[1];
    const int*   lens   = (const int*)d_in[2];
    float*       out    = (float*)d_out;

    norm_kernel<<<(NP * TT) / 8, 256>>>(data);             // idx 0
    d_kernel<<<dim3(5, 5, NP), DTHREADS>>>(data, lens);    // idx 1
    probe0_kernel<<<1, 32>>>();                            // idx 2 (pad)
    dp_kernel<<<NP, 416>>>(lens);                          // idx 3 <- ncu capture slot
    reduce_kernel<<<1, 32>>>(margin, out);                 // idx 4
}